// round 14
// baseline (speedup 1.0000x reference)
#include <cuda_runtime.h>
#include <cuda_fp16.h>
#include <cstdint>

// Spatial RNN, 4 dirs, R=8 steps, C=64. f16 mma.sync, shift-free "v-form".
// x:(8,192,192,64) fp32; W_*:(64,64); out:(8,192,192,256)
//
// Identity: v_s(r) = t_s(r + s*d) satisfies v_s = relu(W v_{s-1}), v_0 = x —
// no shift in the recurrence. Since the m16n8k16 C-fragment packing equals
// the A-fragment packing, A_next = relu(C) is a register rename: the mma
// chain never touches smem. The shift moves to accumulation only:
// acc(r) = sum_s v_s(r - s*d), done by STSM v_s + barrier + LDSM at row
// offset -s*d (guard rows give the zero boundary). Barrier gates only the
// acc side-chain; the next mma issues immediately.
//
// One CTA per line (3072 x 192 thr, 6 warps, m32 x n64 tiles, no dup).
// 2 ping-pong v-buffers, 208 rows x 128B, SW128 swizzle. 2 CTAs/SM.

#define BUFROWS 208                  // rows -8..199 (guards 0..7, 200..207)
#define BUFB (BUFROWS * 128)         // 26624 bytes
#define SMEM_DYN (2 * BUFB + 64)     // 53312

static __device__ __forceinline__ uint32_t smem_u32(const void* p) {
    uint32_t a;
    asm("{ .reg .u64 t; cvta.to.shared.u64 t, %1; cvt.u32.u64 %0, t; }" : "=r"(a) : "l"(p));
    return a;
}
static __device__ __forceinline__ uint32_t pkh2(float lo, float hi) {
    uint32_t r;
    asm("cvt.rn.f16x2.f32 %0, %1, %2;" : "=r"(r) : "f"(hi), "f"(lo));
    return r;
}
static __device__ __forceinline__ uint32_t hmax2z(uint32_t v) {
    uint32_t r;
    asm("max.f16x2 %0, %1, %2;" : "=r"(r) : "r"(v), "r"(0u));
    return r;
}
static __device__ __forceinline__ uint32_t hadd2(uint32_t a, uint32_t b) {
    uint32_t r;
    asm("add.f16x2 %0, %1, %2;" : "=r"(r) : "r"(a), "r"(b));
    return r;
}
static __device__ __forceinline__ void unpkh2(uint32_t v, float& lo, float& hi) {
    asm("{ .reg .f16 l, h; mov.b32 {l, h}, %2; cvt.f32.f16 %0, l; cvt.f32.f16 %1, h; }"
        : "=f"(lo), "=f"(hi) : "r"(v));
}
static __device__ __forceinline__ void ldsm4(uint32_t a[4], uint32_t addr) {
    asm volatile("ldmatrix.sync.aligned.m8n8.x4.shared.b16 {%0,%1,%2,%3}, [%4];"
                 : "=r"(a[0]), "=r"(a[1]), "=r"(a[2]), "=r"(a[3]) : "r"(addr));
}
static __device__ __forceinline__ void stsm4(uint32_t addr, uint32_t r0, uint32_t r1,
                                             uint32_t r2, uint32_t r3) {
    asm volatile("stmatrix.sync.aligned.m8n8.x4.shared.b16 [%0], {%1,%2,%3,%4};"
                 :: "r"(addr), "r"(r0), "r"(r1), "r"(r2), "r"(r3) : "memory");
}
static __device__ __forceinline__ void mma16816h(uint32_t c[2], const uint32_t a[4],
                                                 const uint32_t b[2]) {
    asm volatile(
        "mma.sync.aligned.m16n8k16.row.col.f16.f16.f16.f16 "
        "{%0,%1}, {%2,%3,%4,%5}, {%6,%7}, {%0,%1};"
        : "+r"(c[0]), "+r"(c[1])
        : "r"(a[0]), "r"(a[1]), "r"(a[2]), "r"(a[3]), "r"(b[0]), "r"(b[1]));
}
static __device__ __forceinline__ void sts32(uint32_t addr, uint32_t v) {
    asm volatile("st.shared.b32 [%0], %1;" :: "r"(addr), "r"(v) : "memory");
}

extern "C" __global__ void __launch_bounds__(192, 2)
rnn_kernel(const float* __restrict__ x,
           const float* __restrict__ W_left, const float* __restrict__ W_right,
           const float* __restrict__ W_up,   const float* __restrict__ W_down,
           float* __restrict__ out)
{
    extern __shared__ char dsm[];
    const uint32_t base = (smem_u32(dsm) + 15u) & ~15u;
    const uint32_t B0 = base;
    const uint32_t B1 = base + BUFB;

    const int tid  = threadIdx.x;
    const int lane = tid & 31;
    const int warp = tid >> 5;             // 0..5, m0 = 32*warp
    const int gID  = lane >> 2;
    const int tg   = lane & 3;
    const int m0   = warp * 32;

    // --- geometry ---
    long inBase, outBase;
    int pixIn, pixOut, chBase;
    const float *Wfp, *Wbp;
    {
        int l = blockIdx.x;
        if (l < 1536) {                            // horizontal row
            inBase  = (long)l * (192 * 64);
            outBase = (long)l * (192 * 256);
            pixIn = 64;  pixOut = 256;  chBase = 0;
            Wfp = W_left;  Wbp = W_right;
        } else {                                    // vertical column
            int l2 = l - 1536;
            int b = l2 / 192, w = l2 % 192;
            inBase  = (long)b * (192 * 192 * 64)  + (long)w * 64;
            outBase = (long)b * (192 * 192 * 256) + (long)w * 256;
            pixIn = 192 * 64;  pixOut = 192 * 256;  chBase = 128;
            Wfp = W_up;  Wbp = W_down;
        }
    }
    const float* xl = x + inBase;
    float* ol = out + outBase;

    // --- zero guard rows (0..7 and 200..207) of both buffers, once ---
    for (int i = tid; i < 2 * 16 * 32; i += 192) {
        int bufi = i >> 9;                  // 0 or 1
        int j = (i >> 5) & 15;              // guard row index 0..15
        int w = i & 31;
        int row = (j < 8) ? j : 192 + j;    // rows 0..7, 200..207
        sts32(((bufi ? B1 : B0) + (uint32_t)(row * 128 + w * 4)), 0);
    }
    __syncthreads();

    // LDSM/STSM per-thread row/col decomposition
    const int lrow = (lane & 7) + ((lane >> 3) & 1) * 8;
    const int lcol = (lane >> 4) * 16;
    const int stRow = m0 + lrow + 8;                       // v frame + guard offset
    const uint32_t rxS = (uint32_t)((stRow & 7) << 4);     // 16mt doesn't change row&7
    const uint32_t stB0 = (uint32_t)(stRow * 128);

    #pragma unroll 1
    for (int dir = 0; dir < 2; dir++) {
        const float* Wg = dir ? Wbp : Wfp;

        // --- B fragments (full n64) in registers, from gmem (L2-hot) ---
        uint32_t b[4][8][2];
        #pragma unroll
        for (int kc = 0; kc < 4; kc++)
            #pragma unroll
            for (int nt = 0; nt < 8; nt++) {
                int k0 = kc * 16 + 2 * tg;
                int n  = nt * 8 + gID;
                b[kc][nt][0] = pkh2(__ldg(&Wg[(k0)     * 64 + n]), __ldg(&Wg[(k0 + 1) * 64 + n]));
                b[kc][nt][1] = pkh2(__ldg(&Wg[(k0 + 8) * 64 + n]), __ldg(&Wg[(k0 + 9) * 64 + n]));
            }

        // --- chain state a = v_0 = x, loaded straight from gmem ---
        uint32_t a[2][4][4];
        #pragma unroll
        for (int mt = 0; mt < 2; mt++) {
            int r0 = m0 + 16 * mt + gID;
            const float* p0 = xl + (long)r0 * pixIn + 2 * tg;
            const float* p1 = xl + (long)(r0 + 8) * pixIn + 2 * tg;
            #pragma unroll
            for (int kc = 0; kc < 4; kc++) {
                float2 v00 = *reinterpret_cast<const float2*>(p0 + kc * 16);
                float2 v01 = *reinterpret_cast<const float2*>(p0 + kc * 16 + 8);
                float2 v10 = *reinterpret_cast<const float2*>(p1 + kc * 16);
                float2 v11 = *reinterpret_cast<const float2*>(p1 + kc * 16 + 8);
                a[mt][kc][0] = pkh2(v00.x, v00.y);
                a[mt][kc][1] = pkh2(v10.x, v10.y);
                a[mt][kc][2] = pkh2(v01.x, v01.y);
                a[mt][kc][3] = pkh2(v11.x, v11.y);
            }
        }

        uint32_t acc[2][8][2];
        #pragma unroll
        for (int mt = 0; mt < 2; mt++)
            #pragma unroll
            for (int nt = 0; nt < 8; nt++) { acc[mt][nt][0] = 0u; acc[mt][nt][1] = 0u; }

        #pragma unroll 1
        for (int s = 1; s <= 8; s++) {
            const uint32_t dstb = (s & 1) ? B0 : B1;

            // ---- register-resident chain step: v_s = relu(W v_{s-1}) ----
            #pragma unroll
            for (int mt = 0; mt < 2; mt++) {
                uint32_t Cf[8][2];
                #pragma unroll
                for (int nt = 0; nt < 8; nt++) { Cf[nt][0] = 0u; Cf[nt][1] = 0u; }
                #pragma unroll
                for (int kc = 0; kc < 4; kc++)
                    #pragma unroll
                    for (int nt = 0; nt < 8; nt++)
                        mma16816h(Cf[nt], a[mt][kc], b[kc][nt]);
                #pragma unroll
                for (int nt = 0; nt < 8; nt++) {
                    Cf[nt][0] = hmax2z(Cf[nt][0]);
                    Cf[nt][1] = hmax2z(Cf[nt][1]);
                }
                // store v_s for the shifted accumulation
                uint32_t sa = dstb + stB0 + mt * 2048;
                #pragma unroll
                for (int g = 0; g < 4; g++)
                    stsm4(sa + ((uint32_t)(lcol + g * 32) ^ rxS),
                          Cf[2 * g][0], Cf[2 * g][1], Cf[2 * g + 1][0], Cf[2 * g + 1][1]);
                // rename: A_next = relu(C)  (C-frag packing == A-frag packing)
                #pragma unroll
                for (int kc = 0; kc < 4; kc++) {
                    a[mt][kc][0] = Cf[2 * kc][0];
                    a[mt][kc][1] = Cf[2 * kc][1];
                    a[mt][kc][2] = Cf[2 * kc + 1][0];
                    a[mt][kc][3] = Cf[2 * kc + 1][1];
                }
            }

            __syncthreads();

            // ---- accumulate: acc(r) += v_s(r - s*d) ----
            const int ldRow = m0 + lrow + (dir ? 8 + s : 8 - s);
            const uint32_t rxL = (uint32_t)((ldRow & 7) << 4);
            const uint32_t ldB = (uint32_t)(ldRow * 128);
            #pragma unroll
            for (int mt = 0; mt < 2; mt++) {
                uint32_t t[4][4];
                #pragma unroll
                for (int kc = 0; kc < 4; kc++)
                    ldsm4(t[kc], dstb + ldB + mt * 2048 +
                                 ((uint32_t)(lcol + kc * 32) ^ rxL));
                #pragma unroll
                for (int kc = 0; kc < 4; kc++) {
                    acc[mt][2 * kc][0]     = hadd2(acc[mt][2 * kc][0],     t[kc][0]);
                    acc[mt][2 * kc][1]     = hadd2(acc[mt][2 * kc][1],     t[kc][1]);
                    acc[mt][2 * kc + 1][0] = hadd2(acc[mt][2 * kc + 1][0], t[kc][2]);
                    acc[mt][2 * kc + 1][1] = hadd2(acc[mt][2 * kc + 1][1], t[kc][3]);
                }
            }
        }

        // --- epilogue: out = x + acc ---
        const int cb = chBase + dir * 64;
        #pragma unroll
        for (int mt = 0; mt < 2; mt++) {
            #pragma unroll
            for (int hh = 0; hh < 2; hh++) {
                int gr = m0 + mt * 16 + gID + hh * 8;
                const float* xp = xl + (long)gr * pixIn;
                float* op = ol + (long)gr * pixOut + cb;
                #pragma unroll
                for (int nt = 0; nt < 8; nt++) {
                    int col = nt * 8 + 2 * tg;
                    float a0, a1;
                    unpkh2(acc[mt][nt][hh], a0, a1);
                    float2 xv = *reinterpret_cast<const float2*>(xp + col);
                    *reinterpret_cast<float2*>(op + col) =
                        make_float2(xv.x + a0, xv.y + a1);
                }
            }
        }
        // no extra barrier needed: next dir's first STSM hits the other buffer,
        // and its bar_1 orders the overwrite of this dir's v_8 reads.
    }
}

extern "C" void kernel_launch(void* const* d_in, const int* in_sizes, int n_in,
                              void* d_out, int out_size)
{
    const float* x  = (const float*)d_in[0];
    const float* wl = (const float*)d_in[1];
    const float* wr = (const float*)d_in[2];
    const float* wu = (const float*)d_in[3];
    const float* wd = (const float*)d_in[4];
    float* out = (float*)d_out;

    cudaFuncSetAttribute(rnn_kernel, cudaFuncAttributeMaxDynamicSharedMemorySize, SMEM_DYN);
    rnn_kernel<<<3072, 192, SMEM_DYN>>>(x, wl, wr, wu, wd, out);
}